// round 3
// baseline (speedup 1.0000x reference)
#include <cuda_runtime.h>
#include <cstdint>
#include <cstddef>

#define BB 32
#define SQ 2048
#define SK 2048
#define DD 64
#define TQ 16          // q rows per CTA
#define KT 256         // k rows per smem tile
#define KSTRIDE 68     // padded row stride (floats) for K/V tile -> conflict-free LDS.128
#define NTHREADS 256

// dynamic smem layout (floats):
//   S  : TQ * SK            = 32768 floats (131072 B)  softmax scratch / P matrix
//   KV : KT * KSTRIDE       = 17408 floats ( 69632 B)  K tile, then V tile, then O partials
//   Qs : TQ * DD            =  1024 floats (  4096 B)
#define SMEM_FLOATS (TQ*SK + KT*KSTRIDE + TQ*DD)
#define SMEM_BYTES  (SMEM_FLOATS * 4)

__global__ void __launch_bounds__(NTHREADS, 1)
sdpa_kernel(const float* __restrict__ Qg,
            const float* __restrict__ Kg,
            const float* __restrict__ Vg,
            const int*   __restrict__ Mg,     // bool mask marshaled as 4-byte words
            float* __restrict__ attn_out,
            float* __restrict__ o_out)
{
    extern __shared__ float smem[];
    float* S  = smem;                 // [TQ][SK]
    float* KV = smem + TQ * SK;       // [KT][KSTRIDE]
    float* Qs = KV + KT * KSTRIDE;    // [TQ][DD]

    const int tid   = threadIdx.x;
    const int b     = blockIdx.y;
    const int qbase = blockIdx.x * TQ;

    // ---------------- Phase 0: load Q tile (scaled by 1/sqrt(64) = 0.125) ----------------
    {
        const float4* qg = (const float4*)(Qg + ((size_t)b * SQ + qbase) * DD);
        for (int v = tid; v < TQ * DD / 4; v += NTHREADS) {
            float4 x = qg[v];
            x.x *= 0.125f; x.y *= 0.125f; x.z *= 0.125f; x.w *= 0.125f;
            *(float4*)&Qs[v * 4] = x;   // row stride DD=64, contiguous
        }
    }

    // ---------------- Phase 1: S = (Q*0.125) @ K^T, full row block in smem ----------------
    {
        const int qr = tid >> 6;   // 0..3  -> q rows qr*4 + i
        const int kc = tid & 63;   // 0..63 -> k cols kc + 64*j

        for (int kt = 0; kt < SK / KT; kt++) {
            // load K tile [KT][DD] into KV with padded stride
            const float4* kg = (const float4*)(Kg + ((size_t)b * SK + (size_t)kt * KT) * DD);
            for (int v = tid; v < KT * DD / 4; v += NTHREADS) {
                float4 x = kg[v];
                int row = v >> 4, dch = v & 15;
                *(float4*)&KV[row * KSTRIDE + dch * 4] = x;
            }
            __syncthreads();

            float acc[4][4];
            #pragma unroll
            for (int i = 0; i < 4; i++)
                #pragma unroll
                for (int j = 0; j < 4; j++) acc[i][j] = 0.f;

            #pragma unroll 4
            for (int dc = 0; dc < 16; dc++) {
                float4 qf[4], kf[4];
                #pragma unroll
                for (int i = 0; i < 4; i++)
                    qf[i] = *(const float4*)&Qs[(qr * 4 + i) * DD + dc * 4];
                #pragma unroll
                for (int j = 0; j < 4; j++)
                    kf[j] = *(const float4*)&KV[(kc + 64 * j) * KSTRIDE + dc * 4];
                #pragma unroll
                for (int i = 0; i < 4; i++)
                    #pragma unroll
                    for (int j = 0; j < 4; j++) {
                        acc[i][j] += qf[i].x * kf[j].x;
                        acc[i][j] += qf[i].y * kf[j].y;
                        acc[i][j] += qf[i].z * kf[j].z;
                        acc[i][j] += qf[i].w * kf[j].w;
                    }
            }

            #pragma unroll
            for (int i = 0; i < 4; i++)
                #pragma unroll
                for (int j = 0; j < 4; j++)
                    S[(qr * 4 + i) * SK + kt * KT + kc + 64 * j] = acc[i][j];

            __syncthreads();   // protect KV before next tile load
        }
    }

    // ---------------- Phase 2: masked softmax per row; write attn, keep P in smem ----------
    {
        const int warpid = tid >> 5;
        const int lane   = tid & 31;
        for (int rr = 0; rr < 2; rr++) {
            const int q = warpid * 2 + rr;
            const int4* mrow = (const int4*)(Mg + ((size_t)b * SQ + qbase + q) * SK);
            float4* Srow = (float4*)&S[q * SK];

            // pass A: masked max
            float m = -1e9f;
            #pragma unroll 4
            for (int j = lane; j < SK / 4; j += 32) {
                int4  mk = mrow[j];
                float4 s = Srow[j];
                float v0 = mk.x ? s.x : -1e9f;
                float v1 = mk.y ? s.y : -1e9f;
                float v2 = mk.z ? s.z : -1e9f;
                float v3 = mk.w ? s.w : -1e9f;
                m = fmaxf(m, fmaxf(fmaxf(v0, v1), fmaxf(v2, v3)));
            }
            #pragma unroll
            for (int o = 16; o; o >>= 1) m = fmaxf(m, __shfl_xor_sync(0xffffffffu, m, o));

            // pass B: exp, row sum; stash exp back into S
            float sum = 0.f;
            #pragma unroll 4
            for (int j = lane; j < SK / 4; j += 32) {
                int4  mk = mrow[j];
                float4 s = Srow[j];
                float4 e;
                e.x = __expf((mk.x ? s.x : -1e9f) - m);
                e.y = __expf((mk.y ? s.y : -1e9f) - m);
                e.z = __expf((mk.z ? s.z : -1e9f) - m);
                e.w = __expf((mk.w ? s.w : -1e9f) - m);
                sum += e.x + e.y + e.z + e.w;
                Srow[j] = e;
            }
            #pragma unroll
            for (int o = 16; o; o >>= 1) sum += __shfl_xor_sync(0xffffffffu, sum, o);
            const float inv = 1.0f / sum;

            // pass C: normalize, write attn row (coalesced float4), keep P in smem
            float4* arow = (float4*)(attn_out + ((size_t)b * SQ + qbase + q) * SK);
            #pragma unroll 4
            for (int j = lane; j < SK / 4; j += 32) {
                float4 e = Srow[j];
                e.x *= inv; e.y *= inv; e.z *= inv; e.w *= inv;
                Srow[j] = e;
                arow[j] = e;
            }
        }
        __syncthreads();
    }

    // ---------------- Phase 3: O = P @ V, split-K across two 128-thread groups -------------
    {
        const int g   = tid >> 7;   // 0/1: k-halves of each V tile
        const int t   = tid & 127;
        const int pqr = t >> 5;     // 0..3 -> q rows pqr*4 + i
        const int dc  = t & 31;     // 0..31 -> d cols dc*2 + {0,1}

        float acc[4][2];
        #pragma unroll
        for (int i = 0; i < 4; i++) { acc[i][0] = 0.f; acc[i][1] = 0.f; }

        for (int vt = 0; vt < SK / KT; vt++) {
            __syncthreads();
            const float4* vg = (const float4*)(Vg + ((size_t)b * SK + (size_t)vt * KT) * DD);
            for (int v = tid; v < KT * DD / 4; v += NTHREADS) {
                float4 x = vg[v];
                int row = v >> 4, dch = v & 15;
                *(float4*)&KV[row * KSTRIDE + dch * 4] = x;
            }
            __syncthreads();

            const int kbase = vt * KT + g * 128;
            #pragma unroll 4
            for (int kk = 0; kk < 128; kk += 4) {
                float4 pf[4];
                #pragma unroll
                for (int i = 0; i < 4; i++)
                    pf[i] = *(const float4*)&S[(pqr * 4 + i) * SK + kbase + kk];
                float2 vf[4];
                #pragma unroll
                for (int u = 0; u < 4; u++)
                    vf[u] = *(const float2*)&KV[(g * 128 + kk + u) * KSTRIDE + dc * 2];
                #pragma unroll
                for (int i = 0; i < 4; i++) {
                    acc[i][0] += pf[i].x * vf[0].x; acc[i][1] += pf[i].x * vf[0].y;
                    acc[i][0] += pf[i].y * vf[1].x; acc[i][1] += pf[i].y * vf[1].y;
                    acc[i][0] += pf[i].z * vf[2].x; acc[i][1] += pf[i].z * vf[2].y;
                    acc[i][0] += pf[i].w * vf[3].x; acc[i][1] += pf[i].w * vf[3].y;
                }
            }
        }

        __syncthreads();            // everyone done reading KV as V tile
        float* Op = KV;             // reuse: [2][TQ][DD] partials
        #pragma unroll
        for (int i = 0; i < 4; i++) {
            float2 w; w.x = acc[i][0]; w.y = acc[i][1];
            *(float2*)&Op[((size_t)g * TQ + pqr * 4 + i) * DD + dc * 2] = w;
        }
        __syncthreads();

        float4* orow = (float4*)(o_out + ((size_t)b * SQ + qbase) * DD);
        const float4* p0 = (const float4*)Op;
        const float4* p1 = (const float4*)(Op + TQ * DD);
        for (int v = tid; v < TQ * DD / 4; v += NTHREADS) {
            float4 a = p0[v], c = p1[v];
            a.x += c.x; a.y += c.y; a.z += c.z; a.w += c.w;
            orow[v] = a;
        }
    }
}

extern "C" void kernel_launch(void* const* d_in, const int* in_sizes, int n_in,
                              void* d_out, int out_size)
{
    const float* Q    = (const float*)d_in[0];
    const float* K    = (const float*)d_in[1];
    const float* V    = (const float*)d_in[2];
    const int*   mask = (const int*)d_in[3];   // bool marshaled as 4-byte words

    float* attn = (float*)d_out;                                   // [B, SQ, SK]
    float* outp = attn + (size_t)BB * SQ * SK;                     // [B, SQ, D]

    cudaFuncSetAttribute(sdpa_kernel,
                         cudaFuncAttributeMaxDynamicSharedMemorySize, SMEM_BYTES);

    dim3 grid(SQ / TQ, BB);
    sdpa_kernel<<<grid, NTHREADS, SMEM_BYTES>>>(Q, K, V, mask, attn, outp);
}

// round 5
// speedup vs baseline: 1.9602x; 1.9602x over previous
#include <cuda_runtime.h>
#include <cstdint>
#include <cstddef>

#define BB 32
#define SQ 2048
#define SK 2048
#define DD 64
#define QB 128           // q rows per CTA
#define KB 128           // k cols per tile
#define NT 256
#define NTILES (SK/KB)

#define KSTR 68          // K hi/lo tile row stride (floats)
#define VSTR 72          // V tile row stride
#define PSTR 132         // P tile row stride

// float-index offsets in dynamic smem
#define OFF_KHI 0
#define OFF_KLO (128*KSTR)            // 8704
#define OFF_VT  (OFF_KLO + 128*KSTR)  // 17408
#define OFF_P   (OFF_VT + 128*VSTR)   // 26624
#define SMEM_FLOATS (OFF_P + 128*PSTR)
#define SMEM_BYTES  (SMEM_FLOATS*4)   // 174080 B

__device__ float g_inv[BB * SQ];      // per-row 1/rowsum scratch

static __device__ __forceinline__ uint32_t f2tf(float x) {
    uint32_t r; asm("cvt.rna.tf32.f32 %0, %1;" : "=r"(r) : "f"(x)); return r;
}
static __device__ __forceinline__ void mma8(float& d0, float& d1, float& d2, float& d3,
                                            uint32_t a0, uint32_t a1, uint32_t a2, uint32_t a3,
                                            uint32_t b0, uint32_t b1) {
    asm volatile("mma.sync.aligned.m16n8k8.row.col.f32.tf32.tf32.f32 "
                 "{%0,%1,%2,%3}, {%4,%5,%6,%7}, {%8,%9}, {%0,%1,%2,%3};"
                 : "+f"(d0), "+f"(d1), "+f"(d2), "+f"(d3)
                 : "r"(a0), "r"(a1), "r"(a2), "r"(a3), "r"(b0), "r"(b1));
}

__global__ void __launch_bounds__(NT, 1)
attn_pass1(const float* __restrict__ Qg, const float* __restrict__ Kg,
           const float* __restrict__ Vg, const int* __restrict__ Mg,
           float* __restrict__ attn, float* __restrict__ Og)
{
    extern __shared__ float sm[];
    uint32_t* KHu = (uint32_t*)(sm + OFF_KHI);
    uint32_t* KLu = (uint32_t*)(sm + OFF_KLO);
    uint32_t* VTu = (uint32_t*)(sm + OFF_VT);
    uint32_t* Pu  = (uint32_t*)(sm + OFF_P);

    const int tid  = threadIdx.x;
    const int w    = tid >> 5;
    const int lane = tid & 31;
    const int q    = lane & 3;        // thread-in-group (col within fragment)
    const int g    = lane >> 2;       // group id (row within fragment)
    const int b    = blockIdx.y;
    const int qbase = blockIdx.x * QB;

    const int r0 = w * 16 + g;        // local q row (and r0+8)
    const size_t grow0 = (size_t)b * SQ + qbase + r0;
    const size_t grow1 = grow0 + 8;

    // ---- stage Q (scaled 0.125, hi/lo tf32 split) into KHI/KLO, then lift frags to regs ----
    {
        const float4* Qv = (const float4*)(Qg + ((size_t)b * SQ + qbase) * DD);
        for (int v = tid; v < QB * DD / 4; v += NT) {
            int row = v >> 4, c = (v & 15) * 4;
            float4 x = Qv[v];
            x.x *= 0.125f; x.y *= 0.125f; x.z *= 0.125f; x.w *= 0.125f;
            uint4 hi, lo;
            hi.x = f2tf(x.x); lo.x = f2tf(x.x - __uint_as_float(hi.x));
            hi.y = f2tf(x.y); lo.y = f2tf(x.y - __uint_as_float(hi.y));
            hi.z = f2tf(x.z); lo.z = f2tf(x.z - __uint_as_float(hi.z));
            hi.w = f2tf(x.w); lo.w = f2tf(x.w - __uint_as_float(hi.w));
            *(uint4*)&KHu[row * KSTR + c] = hi;
            *(uint4*)&KLu[row * KSTR + c] = lo;
        }
    }
    __syncthreads();

    uint32_t qhi[8][4], qlo[8][4];
    #pragma unroll
    for (int s = 0; s < 8; s++) {
        const int c0 = s * 8 + q;
        qhi[s][0] = KHu[r0 * KSTR + c0];
        qhi[s][1] = KHu[(r0 + 8) * KSTR + c0];
        qhi[s][2] = KHu[r0 * KSTR + c0 + 4];
        qhi[s][3] = KHu[(r0 + 8) * KSTR + c0 + 4];
        qlo[s][0] = KLu[r0 * KSTR + c0];
        qlo[s][1] = KLu[(r0 + 8) * KSTR + c0];
        qlo[s][2] = KLu[r0 * KSTR + c0 + 4];
        qlo[s][3] = KLu[(r0 + 8) * KSTR + c0 + 4];
    }
    __syncthreads();

    float oacc[8][4];
    #pragma unroll
    for (int i = 0; i < 8; i++)
        oacc[i][0] = oacc[i][1] = oacc[i][2] = oacc[i][3] = 0.f;
    float lsum0 = 0.f, lsum1 = 0.f;

    for (int t = 0; t < NTILES; t++) {
        // ---- load K tile (hi/lo split) + V tile (tf32) ----
        const float4* Kv = (const float4*)(Kg + ((size_t)b * SK + (size_t)t * KB) * DD);
        const float4* Vv = (const float4*)(Vg + ((size_t)b * SK + (size_t)t * KB) * DD);
        for (int v = tid; v < KB * DD / 4; v += NT) {
            int row = v >> 4, c = (v & 15) * 4;
            float4 x = Kv[v];
            uint4 hi, lo;
            hi.x = f2tf(x.x); lo.x = f2tf(x.x - __uint_as_float(hi.x));
            hi.y = f2tf(x.y); lo.y = f2tf(x.y - __uint_as_float(hi.y));
            hi.z = f2tf(x.z); lo.z = f2tf(x.z - __uint_as_float(hi.z));
            hi.w = f2tf(x.w); lo.w = f2tf(x.w - __uint_as_float(hi.w));
            *(uint4*)&KHu[row * KSTR + c] = hi;
            *(uint4*)&KLu[row * KSTR + c] = lo;
            float4 y = Vv[v];
            uint4 vt;
            vt.x = f2tf(y.x); vt.y = f2tf(y.y); vt.z = f2tf(y.z); vt.w = f2tf(y.w);
            *(uint4*)&VTu[row * VSTR + c] = vt;
        }
        __syncthreads();

        // ---- QK (3xTF32) + fused epilogue, one 8-col block at a time ----
        #pragma unroll 1
        for (int nb = 0; nb < 16; nb++) {
            float a0 = 0.f, a1 = 0.f, a2 = 0.f, a3 = 0.f;     // qhi*khi chain
            float c0 = 0.f, c1 = 0.f, c2 = 0.f, c3 = 0.f;     // cross-term chain
            const int nrow = nb * 8 + g;
            #pragma unroll
            for (int s = 0; s < 8; s++) {
                const int cc = s * 8 + q;
                const uint32_t bh0 = KHu[nrow * KSTR + cc];
                const uint32_t bh1 = KHu[nrow * KSTR + cc + 4];
                const uint32_t bl0 = KLu[nrow * KSTR + cc];
                const uint32_t bl1 = KLu[nrow * KSTR + cc + 4];
                mma8(a0, a1, a2, a3, qhi[s][0], qhi[s][1], qhi[s][2], qhi[s][3], bh0, bh1);
                mma8(c0, c1, c2, c3, qlo[s][0], qlo[s][1], qlo[s][2], qlo[s][3], bh0, bh1);
                mma8(c0, c1, c2, c3, qhi[s][0], qhi[s][1], qhi[s][2], qhi[s][3], bl0, bl1);
            }
            const float s00 = a0 + c0, s01 = a1 + c1, s10 = a2 + c2, s11 = a3 + c3;

            const int col = t * KB + nb * 8 + 2 * q;
            const int2 m0 = *(const int2*)(Mg + grow0 * SK + col);
            const int2 m1 = *(const int2*)(Mg + grow1 * SK + col);
            float e00 = m0.x ? __expf(s00) : 0.f;
            float e01 = m0.y ? __expf(s01) : 0.f;
            float e10 = m1.x ? __expf(s10) : 0.f;
            float e11 = m1.y ? __expf(s11) : 0.f;
            float2 w0; w0.x = e00; w0.y = e01;
            float2 w1; w1.x = e10; w1.y = e11;
            *(float2*)(attn + grow0 * SK + col) = w0;
            *(float2*)(attn + grow1 * SK + col) = w1;
            lsum0 += e00 + e01;
            lsum1 += e10 + e11;

            uint2 p0; p0.x = f2tf(e00); p0.y = f2tf(e01);
            uint2 p1; p1.x = f2tf(e10); p1.y = f2tf(e11);
            *(uint2*)&Pu[r0 * PSTR + nb * 8 + 2 * q] = p0;        // warp-private strip
            *(uint2*)&Pu[(r0 + 8) * PSTR + nb * 8 + 2 * q] = p1;
        }

        // ---- O += P @ V (k=128: 16 steps; n=64: 8 blocks) ----
        #pragma unroll 1
        for (int s2 = 0; s2 < 16; s2++) {
            const int cc = s2 * 8 + q;
            const uint32_t pa0 = Pu[r0 * PSTR + cc];
            const uint32_t pa1 = Pu[(r0 + 8) * PSTR + cc];
            const uint32_t pa2 = Pu[r0 * PSTR + cc + 4];
            const uint32_t pa3 = Pu[(r0 + 8) * PSTR + cc + 4];
            const int vr0 = s2 * 8 + q;
            #pragma unroll
            for (int nb2 = 0; nb2 < 8; nb2++) {
                const uint32_t vb0 = VTu[vr0 * VSTR + nb2 * 8 + g];
                const uint32_t vb1 = VTu[(vr0 + 4) * VSTR + nb2 * 8 + g];
                mma8(oacc[nb2][0], oacc[nb2][1], oacc[nb2][2], oacc[nb2][3],
                     pa0, pa1, pa2, pa3, vb0, vb1);
            }
        }
        __syncthreads();   // protect K/V/P smem before next tile load
    }

    // ---- finalize: row sums via butterfly within 4-lane groups ----
    #pragma unroll
    for (int off = 1; off <= 2; off <<= 1) {
        lsum0 += __shfl_xor_sync(0xffffffffu, lsum0, off);
        lsum1 += __shfl_xor_sync(0xffffffffu, lsum1, off);
    }
    const float inv0 = 1.0f / lsum0;
    const float inv1 = 1.0f / lsum1;
    if (q == 0) {
        g_inv[grow0] = inv0;
        g_inv[grow1] = inv1;
    }

    #pragma unroll
    for (int nb2 = 0; nb2 < 8; nb2++) {
        float2 o0; o0.x = oacc[nb2][0] * inv0; o0.y = oacc[nb2][1] * inv0;
        float2 o1; o1.x = oacc[nb2][2] * inv1; o1.y = oacc[nb2][3] * inv1;
        *(float2*)(Og + grow0 * DD + nb2 * 8 + 2 * q) = o0;
        *(float2*)(Og + grow1 * DD + nb2 * 8 + 2 * q) = o1;
    }
}

// ---- pass 2: normalize attn rows by 1/rowsum ----
__global__ void __launch_bounds__(256)
attn_norm(float* __restrict__ attn)
{
    const int row = blockIdx.x;
    const float inv = g_inv[row];
    float4* p = (float4*)(attn + (size_t)row * SK);
    const int i = threadIdx.x;
    #pragma unroll
    for (int k = 0; k < 2; k++) {
        float4 x = p[i + k * 256];
        x.x *= inv; x.y *= inv; x.z *= inv; x.w *= inv;
        p[i + k * 256] = x;
    }
}

extern "C" void kernel_launch(void* const* d_in, const int* in_sizes, int n_in,
                              void* d_out, int out_size)
{
    const float* Q    = (const float*)d_in[0];
    const float* K    = (const float*)d_in[1];
    const float* V    = (const float*)d_in[2];
    const int*   mask = (const int*)d_in[3];

    float* attn = (float*)d_out;                   // [B, SQ, SK]
    float* outp = attn + (size_t)BB * SQ * SK;     // [B, SQ, D]

    cudaFuncSetAttribute(attn_pass1,
                         cudaFuncAttributeMaxDynamicSharedMemorySize, SMEM_BYTES);

    dim3 grid(SQ / QB, BB);
    attn_pass1<<<grid, NT, SMEM_BYTES>>>(Q, K, V, mask, attn, outp);
    attn_norm<<<BB * SQ, 256>>>(attn);
}